// round 9
// baseline (speedup 1.0000x reference)
#include <cuda_runtime.h>

typedef unsigned long long ull;

#define TS      32          // square tile
#define HALO    5
#define KW      11
#define RN      42          // TS + 2*HALO
#define PPX     43          // sxy pitch in (u,v) pairs (ull)
#define HP      33          // h-buffer pitch in float4
#define IMH     2048
#define IMW     2048
#define NCH     3
#define NTHREADS 128
#define GX      64
#define GY      64
#define NBLK    (GX*GY)

#define C1 1.0e-4f
#define C2 9.0e-4f

// per-channel smem layout (floats)
#define OFS_SXY  0                              // RN*PPX ull = 3612 floats
#define OFS_H    (RN*PPX*2)                     // 3612
#define SMEM_FLOATS (OFS_H + RN*HP*4)           // +5544 = 9156 (36624 B)

#define WIDX(k) ((k) <= 5 ? (k) : (10 - (k)))   // symmetric Gaussian taps

__device__ float g_partial[NBLK];
__device__ unsigned int g_flag;   // zero-init; last block resets it

__device__ __forceinline__ ull pack2(float lo, float hi) {
    ull r; asm("mov.b64 %0,{%1,%2};" : "=l"(r) : "f"(lo), "f"(hi)); return r;
}
__device__ __forceinline__ float2 unpack2(ull v) {
    float2 r; asm("mov.b64 {%0,%1},%2;" : "=f"(r.x), "=f"(r.y) : "l"(v)); return r;
}
__device__ __forceinline__ ull fma2(ull a, ull b, ull c) {
    ull d; asm("fma.rn.f32x2 %0,%1,%2,%3;" : "=l"(d) : "l"(a), "l"(b), "l"(c)); return d;
}
__device__ __forceinline__ ull mul2(ull a, ull b) {
    ull d; asm("mul.rn.f32x2 %0,%1,%2;" : "=l"(d) : "l"(a), "l"(b)); return d;
}

__device__ __forceinline__ void load_channel(
    const float* __restrict__ img1, const float* __restrict__ img2,
    float* __restrict__ sxyF, int c, int row0, int col0, int tid)
{
    for (int idx = tid; idx < RN * RN; idx += NTHREADS) {
        int r = idx / RN;
        int p = idx - r * RN;
        int gr = row0 + r, gc = col0 + p;
        float v1 = 0.f, v2 = 0.f;
        if (gr >= 0 && gr < IMH && gc >= 0 && gc < IMW) {
            int off = (gr * IMW + gc) * NCH + c;
            v1 = img1[off];
            v2 = img2[off];
        }
        // zero padding commutes with (u,v) = (x+y, x-y)
        ((float2*)sxyF)[r * PPX + p] = make_float2(v1 + v2, v1 - v2);
    }
}

__device__ __forceinline__ void horiz_item(
    const float* __restrict__ sxyF, float* __restrict__ hF,
    const ull* __restrict__ wwr, int idx)
{
    int r  = idx % RN;
    int j0 = (idx / RN) << 3;
    const ull* puv = (const ull*)sxyF + r * PPX + j0;

    ull auv[8], ass[8];
    #pragma unroll
    for (int o = 0; o < 8; o++) { auv[o] = 0; ass[o] = 0; }

    #pragma unroll
    for (int t = 0; t < 18; t++) {            // 8 + KW - 1
        ull vuv = puv[t];
        ull vss = mul2(vuv, vuv);
        #pragma unroll
        for (int o = 0; o < 8; o++) {
            int k = t - o;
            if (k >= 0 && k < KW) {           // compile-time resolved
                auv[o] = fma2(wwr[WIDX(k)], vuv, auv[o]);
                ass[o] = fma2(wwr[WIDX(k)], vss, ass[o]);
            }
        }
    }
    float4* dst = (float4*)hF + r * HP + j0;
    #pragma unroll
    for (int o = 0; o < 8; o++) {
        float2 a = unpack2(auv[o]);
        float2 b = unpack2(ass[o]);
        dst[o] = make_float4(a.x, a.y, b.x, b.y);
    }
}

__global__ __launch_bounds__(NTHREADS, 6) void ssim_tile_kernel(
    const float* __restrict__ img1,
    const float* __restrict__ img2,
    const float* __restrict__ window,
    float* __restrict__ out)
{
    extern __shared__ float smem[];
    float* sxyF = smem + OFS_SXY;                // (u,v) pairs, one channel
    float* hF   = smem + OFS_H;                  // (U,V,Su,Sv) float4 per column

    const int tid  = threadIdx.x;
    const int wid  = tid >> 5;
    const int lane = tid & 31;

    // ---- separable taps (symmetric): g_k = w2d[5][k] / sqrt(w2d[5][5]), k<=5
    ull wwr[6];
    {
        float g5 = sqrtf(window[5 * KW + 5]);
        #pragma unroll
        for (int k = 0; k < 6; k++) {
            float w = window[5 * KW + k] / g5;
            wwr[k] = pack2(w, w);
        }
    }

    const int row0 = (int)blockIdx.y * TS - HALO;
    const int col0 = (int)blockIdx.x * TS - HALO;

    float lsum = 0.f;

    // ---- prologue: channel 0 load + horizontal ----
    load_channel(img1, img2, sxyF, 0, row0, col0, tid);
    __syncthreads();
    horiz_item(sxyF, hF, wwr, tid);
    if (tid < RN * 4 - NTHREADS) horiz_item(sxyF, hF, wwr, NTHREADS + tid);
    __syncthreads();                              // sxy consumed; h visible

    for (int c = 0; c < NCH; c++) {
        // ---------- fused phase: vertical(c) || load(c+1) ----------------
        // vert reads hF only; load writes sxyF only (horiz(c) already done
        // with sxyF). One sync afterwards protects both for horiz(c+1).
        {
            int tx  = lane;                       // column 0..31
            int ty0 = wid << 3;                   // stack base row 0/8/16/24
            ull aU[8], aS[8];
            #pragma unroll
            for (int o = 0; o < 8; o++) { aU[o] = 0; aS[o] = 0; }

            #pragma unroll
            for (int t = 0; t < 18; t++) {
                int r = ty0 + t;
                float4 h = ((const float4*)hF)[r * HP + tx];
                ull huv = pack2(h.x, h.y);
                ull hss = pack2(h.z, h.w);
                #pragma unroll
                for (int o = 0; o < 8; o++) {
                    int k = t - o;
                    if (k >= 0 && k < KW) {
                        aU[o] = fma2(wwr[WIDX(k)], huv, aU[o]);
                        aS[o] = fma2(wwr[WIDX(k)], hss, aS[o]);
                    }
                }
            }
            #pragma unroll
            for (int o = 0; o < 8; o++) {
                float2 uv = unpack2(aU[o]);      // U = mu1+mu2, V = mu1-mu2
                float2 ss = unpack2(aS[o]);      // Su = E[u^2], Sv = E[v^2]
                float U2 = uv.x * uv.x;
                float V2 = uv.y * uv.y;
                float A  = ss.x - U2;            // = s1+s2+2*s12 (x2 scale)
                float B  = ss.y - V2;            // = s1+s2-2*s12 (x2 scale)
                float num = fmaf(0.5f, U2 - V2, C1) * fmaf(0.5f, A - B, C2);
                float den = fmaf(0.5f, U2 + V2, C1) * fmaf(0.5f, A + B, C2);
                lsum += __fdividef(num, den);
            }
        }
        if (c + 1 < NCH)
            load_channel(img1, img2, sxyF, c + 1, row0, col0, tid);
        __syncthreads();   // h reads done; sxy(c+1) visible

        if (c + 1 < NCH) {
            horiz_item(sxyF, hF, wwr, tid);
            if (tid < RN * 4 - NTHREADS) horiz_item(sxyF, hF, wwr, NTHREADS + tid);
            __syncthreads();                      // h(c+1) visible
        }
    }

    // ---------- block reduction (4 warps) ----------
    #pragma unroll
    for (int s = 16; s > 0; s >>= 1)
        lsum += __shfl_xor_sync(0xffffffffu, lsum, s);
    __shared__ float red[4];
    if (lane == 0) red[wid] = lsum;
    __syncthreads();
    if (tid == 0) {
        float bs = red[0] + red[1] + red[2] + red[3];
        g_partial[blockIdx.y * GX + blockIdx.x] = bs;
    }

    // ---------- last-block finalize (no second launch) ----------
    __shared__ bool amLast;
    __threadfence();
    if (tid == 0) {
        unsigned int n = atomicAdd(&g_flag, 1u);
        amLast = (n == (unsigned)(NBLK - 1));
    }
    __syncthreads();
    if (amLast) {
        double s = 0.0;
        for (int i = tid; i < NBLK; i += NTHREADS)
            s += (double)g_partial[i];
        #pragma unroll
        for (int sft = 16; sft > 0; sft >>= 1)
            s += __shfl_xor_sync(0xffffffffu, s, sft);
        __shared__ double rd[4];
        if (lane == 0) rd[wid] = s;
        __syncthreads();
        if (tid == 0) {
            double t = rd[0] + rd[1] + rd[2] + rd[3];
            out[0] = (float)(1.0 - t / ((double)IMH * IMW * NCH));
            g_flag = 0;                 // reset for next graph replay
        }
    }
}

extern "C" void kernel_launch(void* const* d_in, const int* in_sizes, int n_in,
                              void* d_out, int out_size)
{
    const float* img1 = (const float*)d_in[0];
    const float* img2 = (const float*)d_in[1];
    const float* win  = (const float*)d_in[2];
    float* out = (float*)d_out;
    (void)in_sizes; (void)n_in; (void)out_size;

    const size_t SMEM = (size_t)SMEM_FLOATS * sizeof(float);   // 36624 B
    cudaFuncSetAttribute(ssim_tile_kernel,
                         cudaFuncAttributeMaxDynamicSharedMemorySize, (int)SMEM);

    dim3 grid(GX, GY);
    ssim_tile_kernel<<<grid, NTHREADS, SMEM>>>(img1, img2, win, out);
}

// round 10
// speedup vs baseline: 1.0153x; 1.0153x over previous
#include <cuda_runtime.h>

typedef unsigned long long ull;

#define TS      32          // square tile
#define HALO    5
#define KW      11
#define RN      42          // TS + 2*HALO
#define PPX     43          // sxy pitch in (u,v) pairs (ull)
#define HP      33          // h-buffer pitch in float4
#define IMH     2048
#define IMW     2048
#define NCH     3
#define NTHREADS 192
#define GX      64
#define GY      64
#define NBLK    (GX*GY)

#define C1 1.0e-4f
#define C2 9.0e-4f

// per-channel smem layout (floats)
#define OFS_SXY  0                              // RN*PPX ull = 3612 floats
#define OFS_H    (RN*PPX*2)                     // 3612
#define SMEM_FLOATS (OFS_H + RN*HP*4)           // +5544 = 9156 (36624 B)

#define WIDX(k) ((k) <= 5 ? (k) : (10 - (k)))   // symmetric Gaussian taps

__device__ float g_partial[NBLK];
__device__ unsigned int g_flag;   // zero-init; last block resets it

__device__ __forceinline__ ull pack2(float lo, float hi) {
    ull r; asm("mov.b64 %0,{%1,%2};" : "=l"(r) : "f"(lo), "f"(hi)); return r;
}
__device__ __forceinline__ float2 unpack2(ull v) {
    float2 r; asm("mov.b64 {%0,%1},%2;" : "=f"(r.x), "=f"(r.y) : "l"(v)); return r;
}
__device__ __forceinline__ ull fma2(ull a, ull b, ull c) {
    ull d; asm("fma.rn.f32x2 %0,%1,%2,%3;" : "=l"(d) : "l"(a), "l"(b), "l"(c)); return d;
}
__device__ __forceinline__ ull mul2(ull a, ull b) {
    ull d; asm("mul.rn.f32x2 %0,%1,%2;" : "=l"(d) : "l"(a), "l"(b)); return d;
}

// vertical conv for a stack of NS rows starting at ty0, column tx
template<int NS>
__device__ __forceinline__ float vert_stack(
    const float* __restrict__ hF, const ull* __restrict__ wwr,
    int ty0, int tx)
{
    ull aU[NS], aS[NS];
    #pragma unroll
    for (int o = 0; o < NS; o++) { aU[o] = 0; aS[o] = 0; }

    #pragma unroll
    for (int t = 0; t < NS + KW - 1; t++) {
        int r = ty0 + t;
        float4 h = ((const float4*)hF)[r * HP + tx];
        ull huv = pack2(h.x, h.y);
        ull hss = pack2(h.z, h.w);
        #pragma unroll
        for (int o = 0; o < NS; o++) {
            int k = t - o;
            if (k >= 0 && k < KW) {               // compile-time resolved
                aU[o] = fma2(wwr[WIDX(k)], huv, aU[o]);
                aS[o] = fma2(wwr[WIDX(k)], hss, aS[o]);
            }
        }
    }
    float s = 0.f;
    #pragma unroll
    for (int o = 0; o < NS; o++) {
        float2 uv = unpack2(aU[o]);              // U = mu1+mu2, V = mu1-mu2
        float2 ss = unpack2(aS[o]);              // Su = E[u^2], Sv = E[v^2]
        float U2 = uv.x * uv.x;
        float V2 = uv.y * uv.y;
        float A  = ss.x - U2;                    // = s1+s2+2*s12 (x2 scale)
        float B  = ss.y - V2;                    // = s1+s2-2*s12 (x2 scale)
        float num = fmaf(0.5f, U2 - V2, C1) * fmaf(0.5f, A - B, C2);
        float den = fmaf(0.5f, U2 + V2, C1) * fmaf(0.5f, A + B, C2);
        s += __fdividef(num, den);
    }
    return s;
}

__global__ __launch_bounds__(NTHREADS, 4) void ssim_tile_kernel(
    const float* __restrict__ img1,
    const float* __restrict__ img2,
    const float* __restrict__ window,
    float* __restrict__ out)
{
    extern __shared__ float smem[];
    float* sxyF = smem + OFS_SXY;                // (u,v) pairs, one channel
    float* hF   = smem + OFS_H;                  // (U,V,Su,Sv) float4 per column

    const int tid  = threadIdx.x;
    const int wid  = tid >> 5;
    const int lane = tid & 31;

    // ---- separable taps (symmetric): g_k = w2d[5][k] / sqrt(w2d[5][5]), k<=5
    ull wwr[6];
    {
        float g5 = sqrtf(window[5 * KW + 5]);
        #pragma unroll
        for (int k = 0; k < 6; k++) {
            float w = window[5 * KW + k] / g5;
            wwr[k] = pack2(w, w);
        }
    }

    const int row0 = (int)blockIdx.y * TS - HALO;
    const int col0 = (int)blockIdx.x * TS - HALO;

    float lsum = 0.f;

    for (int c = 0; c < NCH; c++) {
        // ---------- per-channel load: HWC global -> (u,v) pairs in smem -------
        for (int idx = tid; idx < RN * RN; idx += NTHREADS) {
            int r = idx / RN;
            int p = idx - r * RN;
            int gr = row0 + r, gc = col0 + p;
            float v1 = 0.f, v2 = 0.f;
            if (gr >= 0 && gr < IMH && gc >= 0 && gc < IMW) {
                int off = (gr * IMW + gc) * NCH + c;
                v1 = img1[off];
                v2 = img2[off];
            }
            // zero padding commutes with (u,v) = (x+y, x-y)
            ((float2*)sxyF)[r * PPX + p] = make_float2(v1 + v2, v1 - v2);
        }
        __syncthreads();

        // ---------- horizontal pass: 8-wide register-blocked, SINGLE wave -----
        if (tid < RN * 4) {                       // 168 items <= 192 threads
            int r  = tid % RN;
            int j0 = (tid / RN) << 3;
            const ull* puv = (const ull*)sxyF + r * PPX + j0;

            ull auv[8], ass[8];
            #pragma unroll
            for (int o = 0; o < 8; o++) { auv[o] = 0; ass[o] = 0; }

            #pragma unroll
            for (int t = 0; t < 18; t++) {        // 8 + KW - 1
                ull vuv = puv[t];
                ull vss = mul2(vuv, vuv);
                #pragma unroll
                for (int o = 0; o < 8; o++) {
                    int k = t - o;
                    if (k >= 0 && k < KW) {       // compile-time resolved
                        auv[o] = fma2(wwr[WIDX(k)], vuv, auv[o]);
                        ass[o] = fma2(wwr[WIDX(k)], vss, ass[o]);
                    }
                }
            }
            float4* dst = (float4*)hF + r * HP + j0;
            #pragma unroll
            for (int o = 0; o < 8; o++) {
                float2 a = unpack2(auv[o]);
                float2 b = unpack2(ass[o]);
                dst[o] = make_float4(a.x, a.y, b.x, b.y);
            }
        }
        __syncthreads();   // sxy reads done; h writes visible

        // ---------- vertical pass: stacks {6,6,6,6,4,4} over 32 rows ----------
        // warps 0-3: rows [6w, 6w+6);  warps 4-5: rows [24+4(w-4), +4)
        if (wid < 4)
            lsum += vert_stack<6>(hF, wwr, wid * 6, lane);
        else
            lsum += vert_stack<4>(hF, wwr, 24 + (wid - 4) * 4, lane);
        __syncthreads();   // h reads done before next channel overwrites sxy/h
    }

    // ---------- block reduction (6 warps) ----------
    #pragma unroll
    for (int s = 16; s > 0; s >>= 1)
        lsum += __shfl_xor_sync(0xffffffffu, lsum, s);
    __shared__ float red[6];
    if (lane == 0) red[wid] = lsum;
    __syncthreads();
    if (tid == 0) {
        float bs = 0.f;
        #pragma unroll
        for (int i = 0; i < 6; i++) bs += red[i];
        g_partial[blockIdx.y * GX + blockIdx.x] = bs;
    }

    // ---------- last-block finalize (no second launch) ----------
    __shared__ bool amLast;
    __threadfence();
    if (tid == 0) {
        unsigned int n = atomicAdd(&g_flag, 1u);
        amLast = (n == (unsigned)(NBLK - 1));
    }
    __syncthreads();
    if (amLast) {
        double s = 0.0;
        for (int i = tid; i < NBLK; i += NTHREADS)
            s += (double)g_partial[i];
        #pragma unroll
        for (int sft = 16; sft > 0; sft >>= 1)
            s += __shfl_xor_sync(0xffffffffu, s, sft);
        __shared__ double rd[6];
        if (lane == 0) rd[wid] = s;
        __syncthreads();
        if (tid == 0) {
            double t = 0.0;
            #pragma unroll
            for (int i = 0; i < 6; i++) t += rd[i];
            out[0] = (float)(1.0 - t / ((double)IMH * IMW * NCH));
            g_flag = 0;                 // reset for next graph replay
        }
    }
}

extern "C" void kernel_launch(void* const* d_in, const int* in_sizes, int n_in,
                              void* d_out, int out_size)
{
    const float* img1 = (const float*)d_in[0];
    const float* img2 = (const float*)d_in[1];
    const float* win  = (const float*)d_in[2];
    float* out = (float*)d_out;
    (void)in_sizes; (void)n_in; (void)out_size;

    const size_t SMEM = (size_t)SMEM_FLOATS * sizeof(float);   // 36624 B
    cudaFuncSetAttribute(ssim_tile_kernel,
                         cudaFuncAttributeMaxDynamicSharedMemorySize, (int)SMEM);

    dim3 grid(GX, GY);
    ssim_tile_kernel<<<grid, NTHREADS, SMEM>>>(img1, img2, win, out);
}

// round 11
// speedup vs baseline: 1.0774x; 1.0613x over previous
#include <cuda_runtime.h>

typedef unsigned long long ull;

#define TS      32          // square tile
#define HALO    5
#define KW      11
#define RN      42          // TS + 2*HALO
#define PPX     43          // sxy pitch in (u,v) pairs (ull)
#define HP      33          // h-buffer pitch in float4
#define IMH     2048
#define IMW     2048
#define NCH     3
#define NTHREADS 128
#define GX      64
#define GY      64
#define NBLK    (GX*GY)

#define C1 1.0e-4f
#define C2 9.0e-4f

// per-channel smem layout (floats)
#define OFS_SXY  0                              // RN*PPX ull = 3612 floats
#define OFS_H    (RN*PPX*2)                     // 3612
#define SMEM_FLOATS (OFS_H + RN*HP*4)           // +5544 = 9156 (36624 B)

#define WIDX(k) ((k) <= 5 ? (k) : (10 - (k)))   // symmetric Gaussian taps

__device__ float g_partial[NBLK];
__device__ unsigned int g_flag;   // zero-init; last block resets it

__device__ __forceinline__ ull pack2(float lo, float hi) {
    ull r; asm("mov.b64 %0,{%1,%2};" : "=l"(r) : "f"(lo), "f"(hi)); return r;
}
__device__ __forceinline__ float2 unpack2(ull v) {
    float2 r; asm("mov.b64 {%0,%1},%2;" : "=f"(r.x), "=f"(r.y) : "l"(v)); return r;
}
__device__ __forceinline__ ull fma2(ull a, ull b, ull c) {
    ull d; asm("fma.rn.f32x2 %0,%1,%2,%3;" : "=l"(d) : "l"(a), "l"(b), "l"(c)); return d;
}
__device__ __forceinline__ ull mul2(ull a, ull b) {
    ull d; asm("mul.rn.f32x2 %0,%1,%2;" : "=l"(d) : "l"(a), "l"(b)); return d;
}

// -------- load: warp-per-row, division-free; interior CTAs skip all checks ---
__device__ __forceinline__ void load_interior(
    const float* __restrict__ img1, const float* __restrict__ img2,
    float* __restrict__ sxyF, int c, int row0, int col0, int wid, int lane)
{
    const float* b1 = img1 + (row0 * IMW + col0) * NCH + c;
    const float* b2 = img2 + (row0 * IMW + col0) * NCH + c;
    for (int r = wid; r < RN; r += 4) {
        int roff = r * (IMW * NCH);
        float x = b1[roff + lane * NCH];
        float y = b2[roff + lane * NCH];
        ((float2*)sxyF)[r * PPX + lane] = make_float2(x + y, x - y);
        if (lane < RN - 32) {
            int p = 32 + lane;
            float x2 = b1[roff + p * NCH];
            float y2 = b2[roff + p * NCH];
            ((float2*)sxyF)[r * PPX + p] = make_float2(x2 + y2, x2 - y2);
        }
    }
}

__device__ __forceinline__ void load_border(
    const float* __restrict__ img1, const float* __restrict__ img2,
    float* __restrict__ sxyF, int c, int row0, int col0, int wid, int lane)
{
    for (int r = wid; r < RN; r += 4) {
        int gr = row0 + r;
        bool rok = (gr >= 0 && gr < IMH);
        #pragma unroll
        for (int s = 0; s < 2; s++) {
            int p = s * 32 + lane;
            if (p < RN) {
                int gc = col0 + p;
                float v1 = 0.f, v2 = 0.f;
                if (rok && gc >= 0 && gc < IMW) {
                    int off = (gr * IMW + gc) * NCH + c;
                    v1 = img1[off];
                    v2 = img2[off];
                }
                ((float2*)sxyF)[r * PPX + p] = make_float2(v1 + v2, v1 - v2);
            }
        }
    }
}

__global__ __launch_bounds__(NTHREADS, 6) void ssim_tile_kernel(
    const float* __restrict__ img1,
    const float* __restrict__ img2,
    const float* __restrict__ window,
    float* __restrict__ out)
{
    extern __shared__ float smem[];
    float* sxyF = smem + OFS_SXY;                // (u,v) pairs, one channel
    float* hF   = smem + OFS_H;                  // (U,V,Su,Sv) float4 per column

    const int tid  = threadIdx.x;
    const int wid  = tid >> 5;
    const int lane = tid & 31;

    // ---- separable taps (symmetric): g_k = w2d[5][k] / sqrt(w2d[5][5]), k<=5
    ull wwr[6];
    {
        float g5 = sqrtf(window[5 * KW + 5]);
        #pragma unroll
        for (int k = 0; k < 6; k++) {
            float w = window[5 * KW + k] / g5;
            wwr[k] = pack2(w, w);
        }
    }

    const int row0 = (int)blockIdx.y * TS - HALO;
    const int col0 = (int)blockIdx.x * TS - HALO;
    const bool interior = (row0 >= 0) && (row0 + RN <= IMH) &&
                          (col0 >= 0) && (col0 + RN <= IMW);

    // horizontal mapping: 126 items = 3 col-groups x 42 rows, single wave
    const int hg = (tid >= 84) ? 2 : (tid >= 42 ? 1 : 0);
    const int hr = tid - hg * 42;
    const int hj0 = hg * 11;

    float lsum = 0.f;

    for (int c = 0; c < NCH; c++) {
        // ---------- per-channel load ----------
        if (interior)
            load_interior(img1, img2, sxyF, c, row0, col0, wid, lane);
        else
            load_border(img1, img2, sxyF, c, row0, col0, wid, lane);
        __syncthreads();

        // ---------- horizontal pass: uniform 11-wide, single full wave --------
        // group 2 computes 11 outputs but stores only 10 (col 32 discarded;
        // its tap window touches the never-written pitch word col 42, which
        // only feeds the discarded accumulator).
        if (tid < 126) {
            const ull* puv = (const ull*)sxyF + hr * PPX + hj0;

            ull auv[11], ass[11];
            #pragma unroll
            for (int o = 0; o < 11; o++) { auv[o] = 0; ass[o] = 0; }

            #pragma unroll
            for (int t = 0; t < 21; t++) {        // 11 + KW - 1
                ull vuv = puv[t];
                ull vss = mul2(vuv, vuv);
                #pragma unroll
                for (int o = 0; o < 11; o++) {
                    int k = t - o;
                    if (k >= 0 && k < KW) {       // compile-time resolved
                        auv[o] = fma2(wwr[WIDX(k)], vuv, auv[o]);
                        ass[o] = fma2(wwr[WIDX(k)], vss, ass[o]);
                    }
                }
            }
            float4* dst = (float4*)hF + hr * HP + hj0;
            #pragma unroll
            for (int o = 0; o < 11; o++) {
                if (o < 10 || hg < 2) {
                    float2 a = unpack2(auv[o]);
                    float2 b = unpack2(ass[o]);
                    dst[o] = make_float4(a.x, a.y, b.x, b.y);
                }
            }
        }
        __syncthreads();   // sxy reads done; h writes visible

        // ---------- vertical pass: exact single wave (32 cols x 4 warps) ------
        {
            int tx  = lane;                       // column 0..31
            int ty0 = wid << 3;                   // stack base row 0/8/16/24
            ull aU[8], aS[8];
            #pragma unroll
            for (int o = 0; o < 8; o++) { aU[o] = 0; aS[o] = 0; }

            #pragma unroll
            for (int t = 0; t < 18; t++) {
                int r = ty0 + t;
                float4 h = ((const float4*)hF)[r * HP + tx];
                ull huv = pack2(h.x, h.y);
                ull hss = pack2(h.z, h.w);
                #pragma unroll
                for (int o = 0; o < 8; o++) {
                    int k = t - o;
                    if (k >= 0 && k < KW) {
                        aU[o] = fma2(wwr[WIDX(k)], huv, aU[o]);
                        aS[o] = fma2(wwr[WIDX(k)], hss, aS[o]);
                    }
                }
            }
            #pragma unroll
            for (int o = 0; o < 8; o++) {
                float2 uv = unpack2(aU[o]);      // U = mu1+mu2, V = mu1-mu2
                float2 ss = unpack2(aS[o]);      // Su = E[u^2], Sv = E[v^2]
                float U2 = uv.x * uv.x;
                float V2 = uv.y * uv.y;
                float A  = ss.x - U2;            // = s1+s2+2*s12 (x2 scale)
                float B  = ss.y - V2;            // = s1+s2-2*s12 (x2 scale)
                float num = fmaf(0.5f, U2 - V2, C1) * fmaf(0.5f, A - B, C2);
                float den = fmaf(0.5f, U2 + V2, C1) * fmaf(0.5f, A + B, C2);
                lsum += __fdividef(num, den);
            }
        }
        __syncthreads();   // h reads done before next channel overwrites sxy/h
    }

    // ---------- block reduction (4 warps) ----------
    #pragma unroll
    for (int s = 16; s > 0; s >>= 1)
        lsum += __shfl_xor_sync(0xffffffffu, lsum, s);
    __shared__ float red[4];
    if (lane == 0) red[wid] = lsum;
    __syncthreads();
    if (tid == 0) {
        float bs = red[0] + red[1] + red[2] + red[3];
        g_partial[blockIdx.y * GX + blockIdx.x] = bs;
    }

    // ---------- last-block finalize (no second launch) ----------
    __shared__ bool amLast;
    __threadfence();
    if (tid == 0) {
        unsigned int n = atomicAdd(&g_flag, 1u);
        amLast = (n == (unsigned)(NBLK - 1));
    }
    __syncthreads();
    if (amLast) {
        double s = 0.0;
        for (int i = tid; i < NBLK; i += NTHREADS)
            s += (double)g_partial[i];
        #pragma unroll
        for (int sft = 16; sft > 0; sft >>= 1)
            s += __shfl_xor_sync(0xffffffffu, s, sft);
        __shared__ double rd[4];
        if (lane == 0) rd[wid] = s;
        __syncthreads();
        if (tid == 0) {
            double t = rd[0] + rd[1] + rd[2] + rd[3];
            out[0] = (float)(1.0 - t / ((double)IMH * IMW * NCH));
            g_flag = 0;                 // reset for next graph replay
        }
    }
}

extern "C" void kernel_launch(void* const* d_in, const int* in_sizes, int n_in,
                              void* d_out, int out_size)
{
    const float* img1 = (const float*)d_in[0];
    const float* img2 = (const float*)d_in[1];
    const float* win  = (const float*)d_in[2];
    float* out = (float*)d_out;
    (void)in_sizes; (void)n_in; (void)out_size;

    const size_t SMEM = (size_t)SMEM_FLOATS * sizeof(float);   // 36624 B
    cudaFuncSetAttribute(ssim_tile_kernel,
                         cudaFuncAttributeMaxDynamicSharedMemorySize, (int)SMEM);

    dim3 grid(GX, GY);
    ssim_tile_kernel<<<grid, NTHREADS, SMEM>>>(img1, img2, win, out);
}

// round 12
// speedup vs baseline: 1.1008x; 1.0217x over previous
#include <cuda_runtime.h>

typedef unsigned long long ull;

#define TSX     32          // tile width
#define TSY     64          // tile height
#define HALO    5
#define KW      11
#define RNX     42          // TSX + 2*HALO
#define RNY     74          // TSY + 2*HALO
#define PPX     43          // sxy pitch in (u,v) pairs (ull)
#define HP      33          // h-buffer pitch in float4
#define IMH     2048
#define IMW     2048
#define NCH     3
#define NTHREADS 256
#define GX      64          // 2048 / TSX
#define GY      32          // 2048 / TSY
#define NBLK    (GX*GY)

#define C1 1.0e-4f
#define C2 9.0e-4f

// per-channel smem layout (floats)
#define OFS_SXY  0                              // RNY*PPX ull = 6364 floats
#define OFS_H    (RNY*PPX*2)                    // 6364
#define SMEM_FLOATS (OFS_H + RNY*HP*4)          // +9768 = 16132 (64528 B)

#define WIDX(k) ((k) <= 5 ? (k) : (10 - (k)))   // symmetric Gaussian taps

__device__ float g_partial[NBLK];
__device__ unsigned int g_flag;   // zero-init; last block resets it

__device__ __forceinline__ ull pack2(float lo, float hi) {
    ull r; asm("mov.b64 %0,{%1,%2};" : "=l"(r) : "f"(lo), "f"(hi)); return r;
}
__device__ __forceinline__ float2 unpack2(ull v) {
    float2 r; asm("mov.b64 {%0,%1},%2;" : "=f"(r.x), "=f"(r.y) : "l"(v)); return r;
}
__device__ __forceinline__ ull fma2(ull a, ull b, ull c) {
    ull d; asm("fma.rn.f32x2 %0,%1,%2,%3;" : "=l"(d) : "l"(a), "l"(b), "l"(c)); return d;
}
__device__ __forceinline__ ull mul2(ull a, ull b) {
    ull d; asm("mul.rn.f32x2 %0,%1,%2;" : "=l"(d) : "l"(a), "l"(b)); return d;
}

// -------- load: warp-per-row, division-free; interior CTAs skip all checks ---
__device__ __forceinline__ void load_interior(
    const float* __restrict__ img1, const float* __restrict__ img2,
    float* __restrict__ sxyF, int c, int row0, int col0, int wid, int lane)
{
    const float* b1 = img1 + (row0 * IMW + col0) * NCH + c;
    const float* b2 = img2 + (row0 * IMW + col0) * NCH + c;
    for (int r = wid; r < RNY; r += 8) {
        int roff = r * (IMW * NCH);
        float x = b1[roff + lane * NCH];
        float y = b2[roff + lane * NCH];
        ((float2*)sxyF)[r * PPX + lane] = make_float2(x + y, x - y);
        if (lane < RNX - 32) {
            int p = 32 + lane;
            float x2 = b1[roff + p * NCH];
            float y2 = b2[roff + p * NCH];
            ((float2*)sxyF)[r * PPX + p] = make_float2(x2 + y2, x2 - y2);
        }
    }
}

__device__ __forceinline__ void load_border(
    const float* __restrict__ img1, const float* __restrict__ img2,
    float* __restrict__ sxyF, int c, int row0, int col0, int wid, int lane)
{
    for (int r = wid; r < RNY; r += 8) {
        int gr = row0 + r;
        bool rok = (gr >= 0 && gr < IMH);
        #pragma unroll
        for (int s = 0; s < 2; s++) {
            int p = s * 32 + lane;
            if (p < RNX) {
                int gc = col0 + p;
                float v1 = 0.f, v2 = 0.f;
                if (rok && gc >= 0 && gc < IMW) {
                    int off = (gr * IMW + gc) * NCH + c;
                    v1 = img1[off];
                    v2 = img2[off];
                }
                ((float2*)sxyF)[r * PPX + p] = make_float2(v1 + v2, v1 - v2);
            }
        }
    }
}

__global__ __launch_bounds__(NTHREADS, 3) void ssim_tile_kernel(
    const float* __restrict__ img1,
    const float* __restrict__ img2,
    const float* __restrict__ window,
    float* __restrict__ out)
{
    extern __shared__ float smem[];
    float* sxyF = smem + OFS_SXY;                // (u,v) pairs, one channel
    float* hF   = smem + OFS_H;                  // (U,V,Su,Sv) float4 per column

    const int tid  = threadIdx.x;
    const int wid  = tid >> 5;
    const int lane = tid & 31;

    // ---- separable taps (symmetric): g_k = w2d[5][k] / sqrt(w2d[5][5]), k<=5
    ull wwr[6];
    {
        float g5 = sqrtf(window[5 * KW + 5]);
        #pragma unroll
        for (int k = 0; k < 6; k++) {
            float w = window[5 * KW + k] / g5;
            wwr[k] = pack2(w, w);
        }
    }

    const int row0 = (int)blockIdx.y * TSY - HALO;
    const int col0 = (int)blockIdx.x * TSX - HALO;
    const bool interior = (row0 >= 0) && (row0 + RNY <= IMH) &&
                          (col0 >= 0) && (col0 + RNX <= IMW);

    // horizontal mapping: 222 items = 3 col-groups x 74 rows, single wave
    const int hg  = (tid >= 148) ? 2 : (tid >= 74 ? 1 : 0);
    const int hr  = tid - hg * 74;
    const int hj0 = hg * 11;

    float lsum = 0.f;

    for (int c = 0; c < NCH; c++) {
        // ---------- per-channel load ----------
        if (interior)
            load_interior(img1, img2, sxyF, c, row0, col0, wid, lane);
        else
            load_border(img1, img2, sxyF, c, row0, col0, wid, lane);
        __syncthreads();

        // ---------- horizontal pass: uniform 11-wide, single full wave --------
        // group 2 computes 11 outputs but stores only 10 (col 32 discarded;
        // its window reads the never-written pitch word col 42, which only
        // feeds the discarded accumulator).
        if (tid < 222) {
            const ull* puv = (const ull*)sxyF + hr * PPX + hj0;

            ull auv[11], ass[11];
            #pragma unroll
            for (int o = 0; o < 11; o++) { auv[o] = 0; ass[o] = 0; }

            #pragma unroll
            for (int t = 0; t < 21; t++) {        // 11 + KW - 1
                ull vuv = puv[t];
                ull vss = mul2(vuv, vuv);
                #pragma unroll
                for (int o = 0; o < 11; o++) {
                    int k = t - o;
                    if (k >= 0 && k < KW) {       // compile-time resolved
                        auv[o] = fma2(wwr[WIDX(k)], vuv, auv[o]);
                        ass[o] = fma2(wwr[WIDX(k)], vss, ass[o]);
                    }
                }
            }
            float4* dst = (float4*)hF + hr * HP + hj0;
            #pragma unroll
            for (int o = 0; o < 11; o++) {
                if (o < 10 || hg < 2) {
                    float2 a = unpack2(auv[o]);
                    float2 b = unpack2(ass[o]);
                    dst[o] = make_float4(a.x, a.y, b.x, b.y);
                }
            }
        }
        __syncthreads();   // sxy reads done; h writes visible

        // ---------- vertical pass: exact single wave (32 cols x 8 warps) ------
        {
            int tx  = lane;                       // column 0..31
            int ty0 = wid << 3;                   // stack base row 0..56
            ull aU[8], aS[8];
            #pragma unroll
            for (int o = 0; o < 8; o++) { aU[o] = 0; aS[o] = 0; }

            #pragma unroll
            for (int t = 0; t < 18; t++) {
                int r = ty0 + t;
                float4 h = ((const float4*)hF)[r * HP + tx];
                ull huv = pack2(h.x, h.y);
                ull hss = pack2(h.z, h.w);
                #pragma unroll
                for (int o = 0; o < 8; o++) {
                    int k = t - o;
                    if (k >= 0 && k < KW) {
                        aU[o] = fma2(wwr[WIDX(k)], huv, aU[o]);
                        aS[o] = fma2(wwr[WIDX(k)], hss, aS[o]);
                    }
                }
            }
            #pragma unroll
            for (int o = 0; o < 8; o++) {
                float2 uv = unpack2(aU[o]);      // U = mu1+mu2, V = mu1-mu2
                float2 ss = unpack2(aS[o]);      // Su = E[u^2], Sv = E[v^2]
                float U2 = uv.x * uv.x;
                float V2 = uv.y * uv.y;
                float A  = ss.x - U2;            // = s1+s2+2*s12 (x2 scale)
                float B  = ss.y - V2;            // = s1+s2-2*s12 (x2 scale)
                float num = fmaf(0.5f, U2 - V2, C1) * fmaf(0.5f, A - B, C2);
                float den = fmaf(0.5f, U2 + V2, C1) * fmaf(0.5f, A + B, C2);
                lsum += __fdividef(num, den);
            }
        }
        __syncthreads();   // h reads done before next channel overwrites sxy/h
    }

    // ---------- block reduction (8 warps) ----------
    #pragma unroll
    for (int s = 16; s > 0; s >>= 1)
        lsum += __shfl_xor_sync(0xffffffffu, lsum, s);
    __shared__ float red[8];
    if (lane == 0) red[wid] = lsum;
    __syncthreads();
    if (tid == 0) {
        float bs = 0.f;
        #pragma unroll
        for (int i = 0; i < 8; i++) bs += red[i];
        g_partial[blockIdx.y * GX + blockIdx.x] = bs;
    }

    // ---------- last-block finalize (no second launch) ----------
    __shared__ bool amLast;
    __threadfence();
    if (tid == 0) {
        unsigned int n = atomicAdd(&g_flag, 1u);
        amLast = (n == (unsigned)(NBLK - 1));
    }
    __syncthreads();
    if (amLast) {
        double s = 0.0;
        for (int i = tid; i < NBLK; i += NTHREADS)
            s += (double)g_partial[i];
        #pragma unroll
        for (int sft = 16; sft > 0; sft >>= 1)
            s += __shfl_xor_sync(0xffffffffu, s, sft);
        __shared__ double rd[8];
        if (lane == 0) rd[wid] = s;
        __syncthreads();
        if (tid == 0) {
            double t = 0.0;
            #pragma unroll
            for (int i = 0; i < 8; i++) t += rd[i];
            out[0] = (float)(1.0 - t / ((double)IMH * IMW * NCH));
            g_flag = 0;                 // reset for next graph replay
        }
    }
}

extern "C" void kernel_launch(void* const* d_in, const int* in_sizes, int n_in,
                              void* d_out, int out_size)
{
    const float* img1 = (const float*)d_in[0];
    const float* img2 = (const float*)d_in[1];
    const float* win  = (const float*)d_in[2];
    float* out = (float*)d_out;
    (void)in_sizes; (void)n_in; (void)out_size;

    const size_t SMEM = (size_t)SMEM_FLOATS * sizeof(float);   // 64528 B
    cudaFuncSetAttribute(ssim_tile_kernel,
                         cudaFuncAttributeMaxDynamicSharedMemorySize, (int)SMEM);

    dim3 grid(GX, GY);
    ssim_tile_kernel<<<grid, NTHREADS, SMEM>>>(img1, img2, win, out);
}